// round 16
// baseline (speedup 1.0000x reference)
#include <cuda_runtime.h>
#include <cuda_fp16.h>
#include <math.h>

typedef unsigned int u32;

#define ALPHA   8.3f
#define C_IN    64
#define C_OUT   64
#define H_IN    256
#define W_IN    256
#define H_OUT   254
#define W_OUT   254

#define NTHREADS 128
#define TILES_PER_BATCH (127 * 4)   // 127 p-pairs x 4 q-tiles of 64
#define NTILES   (4 * TILES_PER_BATCH)

#define PIXN     264                 // 4 rows x 66 cols
// ---- smem layout (bytes) ----
#define OFF_BIAS 0                   // 64 f               = 256
#define OFF_D    256                 // 4 x 66 f           = 1056
#define OFF_DW   1312                // 9 x 128 f          = 4608
#define OFF_IMGH 5920                // 32 cpair x 264 u32 = 33792
#define SMEM_TOTAL 39712

__device__ __forceinline__ u32 packh2(float lo, float hi) {
    u32 r;
    asm("cvt.rn.f16x2.f32 %0, %1, %2;" : "=r"(r) : "f"(hi), "f"(lo));
    return r;
}
__device__ __forceinline__ u32 hmul2(u32 a, u32 b) {
    u32 r;
    asm("mul.rn.f16x2 %0, %1, %2;" : "=r"(r) : "r"(a), "r"(b));
    return r;
}

// mma.sync m16n8k16 fp16: D(16x8,f32) += A(16x16,f16) * B(16x8,f16)
#define MMA_F16(d, a0, a1, a2, a3, b0, b1)                                  \
    asm volatile(                                                           \
        "mma.sync.aligned.m16n8k16.row.col.f32.f16.f16.f32 "                \
        "{%0,%1,%2,%3}, {%4,%5,%6,%7}, {%8,%9}, {%0,%1,%2,%3};"             \
        : "+f"((d)[0]), "+f"((d)[1]), "+f"((d)[2]), "+f"((d)[3])            \
        : "r"(a0), "r"(a1), "r"(a2), "r"(a3), "r"(b0), "r"(b1))

// W pre-packed fp16 B-fragments: [kc16(36)][j(4)][lane(32)] uint4.
__device__ __align__(16) uint4 g_wh[36 * 4 * 32];

__global__ void prep_w(const float* __restrict__ w) {
    int idx = blockIdx.x * blockDim.x + threadIdx.x;
    if (idx >= 36 * 4 * 32) return;
    int lane = idx & 31;
    int j    = (idx >> 5) & 3;
    int kc16 = idx >> 7;
    int kl = kc16 >> 2, cq = kc16 & 3;
    int g = lane >> 2, t = lane & 3;
    int c0 = cq * 16 + 2 * t;
    int oce = (2 * j) * 8 + g;
    int oco = oce + 8;
    uint4 v;
    v.x = packh2(w[(oce * C_IN + c0)     * 9 + kl], w[(oce * C_IN + c0 + 1) * 9 + kl]);
    v.y = packh2(w[(oce * C_IN + c0 + 8) * 9 + kl], w[(oce * C_IN + c0 + 9) * 9 + kl]);
    v.z = packh2(w[(oco * C_IN + c0)     * 9 + kl], w[(oco * C_IN + c0 + 1) * 9 + kl]);
    v.w = packh2(w[(oco * C_IN + c0 + 8) * 9 + kl], w[(oco * C_IN + c0 + 9) * 9 + kl]);
    g_wh[idx] = v;
}

__global__ __launch_bounds__(NTHREADS, 4)
void depthconv_mma(const float* __restrict__ img,
                   const float* __restrict__ depth,
                   const float* __restrict__ bias,
                   float* __restrict__ out) {
    extern __shared__ char smem[];
    float* s_b    = (float*)(smem + OFF_BIAS);
    float* s_d    = (float*)(smem + OFF_D);
    float* s_dw   = (float*)(smem + OFF_DW);
    u32*   s_imgh = (u32*)  (smem + OFF_IMGH);   // [cpair(32)][pix(264)]

    const int tid  = threadIdx.x;
    const int lane = tid & 31;
    const int wid  = tid >> 5;          // 4 warps: each 2 rows x 16q x 64 oc
    const int g    = lane >> 2;
    const int t    = lane & 3;
    const int qw   = wid * 16;          // q base of this warp's strip

    const int tIdx = blockIdx.x;
    const int b  = tIdx / TILES_PER_BATCH;
    const int r  = tIdx - b * TILES_PER_BATCH;
    const int p0 = (r >> 2) << 1;       // 0..252
    const int q0 = (r & 3) << 6;
    const int qcnt = min(64, W_OUT - q0);

    // ---- stage bias + depth halo (4 x 66) ----
    if (tid < C_OUT) s_b[tid] = bias[tid];
    for (int i = tid; i < 264; i += NTHREADS) {
        int rr = i / 66, cc = i - rr * 66;
        s_d[i] = depth[(size_t)b * H_IN * W_IN + (p0 + rr) * W_IN +
                       min(q0 + cc, W_IN - 1)];
    }
    // ---- stage img as fp16x2 channel pairs: s_imgh[cpair][pix] ----
    {
        const float* ip = img + (size_t)b * C_IN * H_IN * W_IN;
        const size_t HW = (size_t)H_IN * W_IN;
        for (int i = tid; i < 32 * PIXN; i += NTHREADS) {
            int cp  = i / PIXN;
            int pix = i - cp * PIXN;
            int rr  = pix / 66, cc = pix - rr * 66;
            size_t go = ((size_t)(2 * cp) * H_IN + (p0 + rr)) * W_IN +
                        min(q0 + cc, W_IN - 1);
            s_imgh[cp * PIXN + pix] = packh2(ip[go], ip[go + HW]);
        }
    }
    __syncthreads();
    // ---- dw[kl][m] (channel-independent) ----
    for (int i = tid; i < 1152; i += NTHREADS) {
        int kl = i >> 7, m = i & 127;
        int mpr = m >> 6, qq = m & 63;
        int k = kl / 3, l = kl - k * 3;
        float cen = s_d[(mpr + 1) * 66 + qq + 1];
        s_dw[i] = __expf(-ALPHA * fabsf(s_d[(mpr + k) * 66 + qq + l] - cen));
    }
    __syncthreads();

    float acc[2][8][4];
#pragma unroll
    for (int mb = 0; mb < 2; mb++)
#pragma unroll
        for (int nb = 0; nb < 8; nb++)
#pragma unroll
            for (int rr = 0; rr < 4; rr++) acc[mb][nb][rr] = 0.f;

    // ---- K loop: kl outer (not unrolled), cq inner x4 (16 channels each) ----
    const uint4* wlane = g_wh + lane;
    for (int k = 0; k < 3; k++) {
#pragma unroll 1
        for (int l = 0; l < 3; l++) {
            const int kl = k * 3 + l;
            // dw for both output rows (mb = row within p-pair)
            const float* dwp0 = s_dw + kl * 128 + qw;        // row 0
            const float* dwp1 = dwp0 + 64;                   // row 1
            const u32 dwA0 = packh2(dwp0[g],     dwp0[g]);
            const u32 dwA1 = packh2(dwp0[g + 8], dwp0[g + 8]);
            const u32 dwB0 = packh2(dwp1[g],     dwp1[g]);
            const u32 dwB1 = packh2(dwp1[g + 8], dwp1[g + 8]);
            const int pixbase0 = k * 66 + l + qw;            // input row k
            // row 1 input = pixbase0 + 66

#pragma unroll
            for (int cq = 0; cq < 4; cq++) {
                const uint4* wf = wlane + (size_t)(kl * 4 + cq) * 128;
                uint4 bq0 = __ldg(wf);
                uint4 bq1 = __ldg(wf + 32);
                uint4 bq2 = __ldg(wf + 64);
                uint4 bq3 = __ldg(wf + 96);

                const u32* pc  = s_imgh + (cq * 8 + t) * PIXN + pixbase0;
                const u32* pc4 = pc + 4 * PIXN;    // channels +8

                // mb0 (output row 0)
                u32 x0 = hmul2(pc [g],     dwA0);
                u32 x1 = hmul2(pc [g + 8], dwA1);
                u32 x2 = hmul2(pc4[g],     dwA0);
                u32 x3 = hmul2(pc4[g + 8], dwA1);
                // mb1 (output row 1): input row k+1 = +66
                u32 y0 = hmul2(pc [66 + g],     dwB0);
                u32 y1 = hmul2(pc [66 + g + 8], dwB1);
                u32 y2 = hmul2(pc4[66 + g],     dwB0);
                u32 y3 = hmul2(pc4[66 + g + 8], dwB1);

                MMA_F16(acc[0][0], x0, x1, x2, x3, bq0.x, bq0.y);
                MMA_F16(acc[1][0], y0, y1, y2, y3, bq0.x, bq0.y);
                MMA_F16(acc[0][1], x0, x1, x2, x3, bq0.z, bq0.w);
                MMA_F16(acc[1][1], y0, y1, y2, y3, bq0.z, bq0.w);
                MMA_F16(acc[0][2], x0, x1, x2, x3, bq1.x, bq1.y);
                MMA_F16(acc[1][2], y0, y1, y2, y3, bq1.x, bq1.y);
                MMA_F16(acc[0][3], x0, x1, x2, x3, bq1.z, bq1.w);
                MMA_F16(acc[1][3], y0, y1, y2, y3, bq1.z, bq1.w);
                MMA_F16(acc[0][4], x0, x1, x2, x3, bq2.x, bq2.y);
                MMA_F16(acc[1][4], y0, y1, y2, y3, bq2.x, bq2.y);
                MMA_F16(acc[0][5], x0, x1, x2, x3, bq2.z, bq2.w);
                MMA_F16(acc[1][5], y0, y1, y2, y3, bq2.z, bq2.w);
                MMA_F16(acc[0][6], x0, x1, x2, x3, bq3.x, bq3.y);
                MMA_F16(acc[1][6], y0, y1, y2, y3, bq3.x, bq3.y);
                MMA_F16(acc[0][7], x0, x1, x2, x3, bq3.z, bq3.w);
                MMA_F16(acc[1][7], y0, y1, y2, y3, bq3.z, bq3.w);
            }
        }
    }

    // ---- epilogue: bias + store ----
    const int qq0 = qw + g;
#pragma unroll
    for (int mb = 0; mb < 2; mb++) {
#pragma unroll
        for (int nb = 0; nb < 8; nb++) {
            const int oc = nb * 8 + t * 2;
            const float bs0 = s_b[oc], bs1 = s_b[oc + 1];
            const size_t base =
                (((size_t)b * C_OUT + oc) * H_OUT + (p0 + mb)) * W_OUT + q0;
            if (qq0 < qcnt) {
                out[base + qq0]                         = acc[mb][nb][0] + bs0;
                out[base + (size_t)H_OUT * W_OUT + qq0] = acc[mb][nb][1] + bs1;
            }
            if (qq0 + 8 < qcnt) {
                out[base + qq0 + 8]                         = acc[mb][nb][2] + bs0;
                out[base + (size_t)H_OUT * W_OUT + qq0 + 8] = acc[mb][nb][3] + bs1;
            }
        }
    }
}

extern "C" void kernel_launch(void* const* d_in, const int* in_sizes, int n_in,
                              void* d_out, int out_size) {
    const float* img    = nullptr;
    const float* depth  = nullptr;
    const float* weight = nullptr;
    const float* bias   = nullptr;

    for (int i = 0; i < n_in; i++) {
        switch (in_sizes[i]) {
            case 4 * C_IN * H_IN * W_IN: img    = (const float*)d_in[i]; break;
            case 4 * 1 * H_IN * W_IN:    depth  = (const float*)d_in[i]; break;
            case C_OUT * C_IN * 9:       weight = (const float*)d_in[i]; break;
            case C_OUT:                  bias   = (const float*)d_in[i]; break;
            default: break;
        }
    }

    cudaFuncSetAttribute(depthconv_mma,
                         cudaFuncAttributeMaxDynamicSharedMemorySize, SMEM_TOTAL);

    prep_w<<<(36 * 4 * 32 + 255) / 256, 256>>>(weight);
    depthconv_mma<<<NTILES, NTHREADS, SMEM_TOTAL>>>(img, depth, bias, (float*)d_out);
}

// round 17
// speedup vs baseline: 1.4391x; 1.4391x over previous
#include <cuda_runtime.h>
#include <cuda_fp16.h>
#include <math.h>

typedef unsigned int u32;

#define ALPHA   8.3f
#define C_IN    64
#define C_OUT   64
#define H_IN    256
#define W_IN    256
#define H_OUT   254
#define W_OUT   254

#define NTHREADS 256
#define TILES_PER_BATCH (127 * 4)   // 127 p-pairs x 4 q-tiles of 64
#define NTILES   (4 * TILES_PER_BATCH)

#define ROWSTR   68                  // img row stride (u32) - 16B aligned rows
#define CPSTR    280                 // u32 stride per cpair (t offsets {0,24,16,8} banks)
// ---- smem layout (bytes) ----
#define OFF_BIAS 0                   // 64 f                = 256
#define OFF_D    256                 // 4 x 66 f            = 1056
#define OFF_DW   1312                // 9 x 128 u32         = 4608
#define OFF_IMGH 5920                // 32 cpair x 280 u32  = 35840
#define SMEM_TOTAL 41760

__device__ __forceinline__ u32 packh2(float lo, float hi) {
    u32 r;
    asm("cvt.rn.f16x2.f32 %0, %1, %2;" : "=r"(r) : "f"(hi), "f"(lo));
    return r;
}
__device__ __forceinline__ u32 hmul2(u32 a, u32 b) {
    u32 r;
    asm("mul.rn.f16x2 %0, %1, %2;" : "=r"(r) : "r"(a), "r"(b));
    return r;
}

// mma.sync m16n8k16 fp16: D(16x8,f32) += A(16x16,f16) * B(16x8,f16)
#define MMA_F16(d, a0, a1, a2, a3, b0, b1)                                  \
    asm volatile(                                                           \
        "mma.sync.aligned.m16n8k16.row.col.f32.f16.f16.f32 "                \
        "{%0,%1,%2,%3}, {%4,%5,%6,%7}, {%8,%9}, {%0,%1,%2,%3};"             \
        : "+f"((d)[0]), "+f"((d)[1]), "+f"((d)[2]), "+f"((d)[3])            \
        : "r"(a0), "r"(a1), "r"(a2), "r"(a3), "r"(b0), "r"(b1))

// W pre-packed fp16 B-fragments: [kc16(36)][j(4)][lane(32)] uint4.
__device__ __align__(16) uint4 g_wh[36 * 4 * 32];

__global__ void prep_w(const float* __restrict__ w) {
    int idx = blockIdx.x * blockDim.x + threadIdx.x;
    if (idx >= 36 * 4 * 32) return;
    int lane = idx & 31;
    int j    = (idx >> 5) & 3;
    int kc16 = idx >> 7;
    int kl = kc16 >> 2, cq = kc16 & 3;
    int g = lane >> 2, t = lane & 3;
    int c0 = cq * 16 + 2 * t;
    int oce = (2 * j) * 8 + g;
    int oco = oce + 8;
    uint4 v;
    v.x = packh2(w[(oce * C_IN + c0)     * 9 + kl], w[(oce * C_IN + c0 + 1) * 9 + kl]);
    v.y = packh2(w[(oce * C_IN + c0 + 8) * 9 + kl], w[(oce * C_IN + c0 + 9) * 9 + kl]);
    v.z = packh2(w[(oco * C_IN + c0)     * 9 + kl], w[(oco * C_IN + c0 + 1) * 9 + kl]);
    v.w = packh2(w[(oco * C_IN + c0 + 8) * 9 + kl], w[(oco * C_IN + c0 + 9) * 9 + kl]);
    g_wh[idx] = v;
}

__global__ __launch_bounds__(NTHREADS, 3)
void depthconv_mma(const float* __restrict__ img,
                   const float* __restrict__ depth,
                   const float* __restrict__ bias,
                   float* __restrict__ out) {
    extern __shared__ char smem[];
    float* s_b    = (float*)(smem + OFF_BIAS);
    float* s_d    = (float*)(smem + OFF_D);
    u32*   s_dwh  = (u32*)  (smem + OFF_DW);     // pre-packed dup f16x2
    u32*   s_imgh = (u32*)  (smem + OFF_IMGH);   // [cpair(32)][row(4)*68+cc]

    const int tid  = threadIdx.x;
    const int lane = tid & 31;
    const int wid  = tid >> 5;          // 8 warps: each 16 M-pixels x 64 oc
    const int g    = lane >> 2;
    const int t    = lane & 3;
    const int pr   = wid >> 2;          // output row within p-pair
    const int qw   = (wid & 3) * 16;    // q base of this warp's strip

    const int tIdx = blockIdx.x;
    const int b  = tIdx / TILES_PER_BATCH;
    const int r  = tIdx - b * TILES_PER_BATCH;
    const int p0 = (r >> 2) << 1;       // 0..252
    const int q0 = (r & 3) << 6;
    const int qcnt = min(64, W_OUT - q0);
    const size_t HW = (size_t)H_IN * W_IN;

    // ---- stage bias + depth halo (4 x 66) ----
    if (tid < C_OUT) s_b[tid] = bias[tid];
    for (int i = tid; i < 264; i += NTHREADS) {
        int rr = i / 66, cc = i - rr * 66;
        s_d[i] = depth[(size_t)b * HW + (p0 + rr) * W_IN + min(q0 + cc, W_IN - 1)];
    }
    // ---- stage img as fp16x2 channel pairs (vectorized) ----
    {
        const float* ip = img + (size_t)b * C_IN * HW;
        // main body: cc in [0,64) via float4 (q0+c4+3 <= 255 always)
        for (int i = tid; i < 32 * 4 * 16; i += NTHREADS) {
            int cp  = i >> 6;
            int rem = i & 63;
            int rr  = rem >> 4;
            int c4  = (rem & 15) << 2;
            const float* b0p = ip + (size_t)(2 * cp) * HW +
                               (size_t)(p0 + rr) * W_IN + q0 + c4;
            float4 v0 = *reinterpret_cast<const float4*>(b0p);
            float4 v1 = *reinterpret_cast<const float4*>(b0p + HW);
            uint4 o;
            o.x = packh2(v0.x, v1.x);
            o.y = packh2(v0.y, v1.y);
            o.z = packh2(v0.z, v1.z);
            o.w = packh2(v0.w, v1.w);
            *reinterpret_cast<uint4*>(&s_imgh[cp * CPSTR + rr * ROWSTR + c4]) = o;
        }
        // tail: cc = 64, 65 (clamped) — exactly 256 items
        {
            int cp  = tid >> 3;
            int rem = tid & 7;
            int rr  = rem >> 1;
            int cc  = 64 + (rem & 1);
            size_t go = (size_t)(2 * cp) * HW + (size_t)(p0 + rr) * W_IN +
                        min(q0 + cc, W_IN - 1);
            s_imgh[cp * CPSTR + rr * ROWSTR + cc] = packh2(ip[go], ip[go + HW]);
        }
    }
    __syncthreads();
    // ---- dw[kl][m] pre-packed as dup f16x2 ----
    for (int i = tid; i < 1152; i += NTHREADS) {
        int kl = i >> 7, m = i & 127;
        int mpr = m >> 6, qq = m & 63;
        int k = kl / 3, l = kl - k * 3;
        float cen = s_d[(mpr + 1) * 66 + qq + 1];
        float v = __expf(-ALPHA * fabsf(s_d[(mpr + k) * 66 + qq + l] - cen));
        s_dwh[i] = packh2(v, v);
    }
    __syncthreads();

    float acc[8][4];
#pragma unroll
    for (int nb = 0; nb < 8; nb++)
#pragma unroll
        for (int rr = 0; rr < 4; rr++) acc[nb][rr] = 0.f;

    // ---- K loop: k rolled, l fully unrolled (3 bodies ~ fits L0 I$) ----
    const uint4* wlane = g_wh + lane;
#pragma unroll 1
    for (int k = 0; k < 3; k++) {
#pragma unroll
        for (int l = 0; l < 3; l++) {
            const int kl = k * 3 + l;
            const u32* dwp = s_dwh + kl * 128 + pr * 64 + qw;
            const u32 dwh0 = dwp[g];
            const u32 dwh1 = dwp[g + 8];
            const int pixbase = (pr + k) * ROWSTR + l + qw;

#pragma unroll
            for (int cq = 0; cq < 4; cq++) {
                const uint4* wf = wlane + (size_t)(kl * 4 + cq) * 128;
                uint4 bq0 = __ldg(wf);
                uint4 bq1 = __ldg(wf + 32);
                uint4 bq2 = __ldg(wf + 64);
                uint4 bq3 = __ldg(wf + 96);

                const u32* pc  = s_imgh + (cq * 8 + t) * CPSTR + pixbase;
                const u32* pc4 = pc + 4 * CPSTR;    // channels +8
                u32 a0 = hmul2(pc [g],     dwh0);
                u32 a1 = hmul2(pc [g + 8], dwh1);
                u32 a2 = hmul2(pc4[g],     dwh0);
                u32 a3 = hmul2(pc4[g + 8], dwh1);

                MMA_F16(acc[0], a0, a1, a2, a3, bq0.x, bq0.y);
                MMA_F16(acc[1], a0, a1, a2, a3, bq0.z, bq0.w);
                MMA_F16(acc[2], a0, a1, a2, a3, bq1.x, bq1.y);
                MMA_F16(acc[3], a0, a1, a2, a3, bq1.z, bq1.w);
                MMA_F16(acc[4], a0, a1, a2, a3, bq2.x, bq2.y);
                MMA_F16(acc[5], a0, a1, a2, a3, bq2.z, bq2.w);
                MMA_F16(acc[6], a0, a1, a2, a3, bq3.x, bq3.y);
                MMA_F16(acc[7], a0, a1, a2, a3, bq3.z, bq3.w);
            }
        }
    }

    // ---- epilogue: bias + store ----
    const int qq0 = qw + g;
#pragma unroll
    for (int nb = 0; nb < 8; nb++) {
        const int oc = nb * 8 + t * 2;
        const float bs0 = s_b[oc], bs1 = s_b[oc + 1];
        const size_t base =
            (((size_t)b * C_OUT + oc) * H_OUT + (p0 + pr)) * W_OUT + q0;
        if (qq0 < qcnt) {
            out[base + qq0]                         = acc[nb][0] + bs0;
            out[base + (size_t)H_OUT * W_OUT + qq0] = acc[nb][1] + bs1;
        }
        if (qq0 + 8 < qcnt) {
            out[base + qq0 + 8]                         = acc[nb][2] + bs0;
            out[base + (size_t)H_OUT * W_OUT + qq0 + 8] = acc[nb][3] + bs1;
        }
    }
}

extern "C" void kernel_launch(void* const* d_in, const int* in_sizes, int n_in,
                              void* d_out, int out_size) {
    const float* img    = nullptr;
    const float* depth  = nullptr;
    const float* weight = nullptr;
    const float* bias   = nullptr;

    for (int i = 0; i < n_in; i++) {
        switch (in_sizes[i]) {
            case 4 * C_IN * H_IN * W_IN: img    = (const float*)d_in[i]; break;
            case 4 * 1 * H_IN * W_IN:    depth  = (const float*)d_in[i]; break;
            case C_OUT * C_IN * 9:       weight = (const float*)d_in[i]; break;
            case C_OUT:                  bias   = (const float*)d_in[i]; break;
            default: break;
        }
    }

    cudaFuncSetAttribute(depthconv_mma,
                         cudaFuncAttributeMaxDynamicSharedMemorySize, SMEM_TOTAL);

    prep_w<<<(36 * 4 * 32 + 255) / 256, 256>>>(weight);
    depthconv_mma<<<NTILES, NTHREADS, SMEM_TOTAL>>>(img, depth, bias, (float*)d_out);
}